// round 8
// baseline (speedup 1.0000x reference)
#include <cuda_runtime.h>
#include <cstdint>

// Shift op: x[32,64,56,56] -> out[32,576,56,56]
// out[n, c*9 + s, y, x] = x[n, c, y + s/3 - 1, x + s%3 - 1], zero-padded.
//
// R8: 256-bit (v8.b32) global loads and stores — sm_103a supports them and
// W=56 floats splits into exactly 7 aligned 32B chunks per row.
// One thread per (nc, y, x8): 3 LDG.256 (rows y-1,y,y+1) + 6 edge scalars,
// 9 STG.256 outputs. A warp's store covers 1024B contiguous per instruction.

#define N_  32
#define C_  64
#define H_  56
#define W_  56
#define W8 (W_ / 8)      // 7 float8 per row

struct F8 { uint32_t r[8]; };

__device__ __forceinline__ F8 ldg256(const float* p) {
    F8 v;
    asm volatile(
        "ld.global.nc.L2::evict_last.v8.b32 {%0,%1,%2,%3,%4,%5,%6,%7}, [%8];"
        : "=r"(v.r[0]), "=r"(v.r[1]), "=r"(v.r[2]), "=r"(v.r[3]),
          "=r"(v.r[4]), "=r"(v.r[5]), "=r"(v.r[6]), "=r"(v.r[7])
        : "l"(p));
    return v;
}

__device__ __forceinline__ void stg256(float* p, const F8& v) {
    asm volatile(
        "st.global.cs.v8.b32 [%0], {%1,%2,%3,%4,%5,%6,%7,%8};"
        :: "l"(p),
           "r"(v.r[0]), "r"(v.r[1]), "r"(v.r[2]), "r"(v.r[3]),
           "r"(v.r[4]), "r"(v.r[5]), "r"(v.r[6]), "r"(v.r[7])
        : "memory");
}

__global__ __launch_bounds__(256) void shift_kernel(
    const float* __restrict__ in, float* __restrict__ out, int total)
{
    int idx = blockIdx.x * blockDim.x + threadIdx.x;
    if (idx >= total) return;

    // idx -> (nc, y, x8)
    int x8 = idx % W8;
    int t  = idx / W8;
    int y  = t % H_;
    int nc = t / H_;

    int x0 = x8 * 8;
    const float* plane = in + (long long)nc * (H_ * W_);

    F8       v[3];
    uint32_t lft[3], rgt[3];
    #pragma unroll
    for (int dy = 0; dy < 3; dy++) {
        int sy = y + dy - 1;
        if ((unsigned)sy < (unsigned)H_) {
            const float* row = plane + sy * W_;
            v[dy] = ldg256(row + x0);
            lft[dy] = (x0 > 0)      ? __float_as_uint(__ldg(row + x0 - 1)) : 0u;
            rgt[dy] = (x0 + 8 < W_) ? __float_as_uint(__ldg(row + x0 + 8)) : 0u;
        } else {
            #pragma unroll
            for (int i = 0; i < 8; i++) v[dy].r[i] = 0u;
            lft[dy] = 0u;
            rgt[dy] = 0u;
        }
    }

    // out base (in floats) for (nc, s=0, y, x8)
    float* obase = out + ((long long)nc * 9) * (H_ * W_) + y * W_ + x0;
    const int sstride = H_ * W_;   // one s-plane in floats

    #pragma unroll
    for (int dy = 0; dy < 3; dy++) {
        const F8& b = v[dy];
        F8 a, c;
        a.r[0] = lft[dy];
        #pragma unroll
        for (int i = 0; i < 7; i++) { a.r[i + 1] = b.r[i]; c.r[i] = b.r[i + 1]; }
        c.r[7] = rgt[dy];
        stg256(obase + (dy * 3 + 0) * sstride, a);
        stg256(obase + (dy * 3 + 1) * sstride, b);
        stg256(obase + (dy * 3 + 2) * sstride, c);
    }
}

extern "C" void kernel_launch(void* const* d_in, const int* in_sizes, int n_in,
                              void* d_out, int out_size) {
    const float* x = (const float*)d_in[0];
    float* out = (float*)d_out;
    int total = N_ * C_ * H_ * W8;   // 802,816 threads
    int threads = 256;
    int blocks = (total + threads - 1) / threads;
    shift_kernel<<<blocks, threads>>>(x, out, total);
}